// round 4
// baseline (speedup 1.0000x reference)
#include <cuda_runtime.h>
#include <cuda_bf16.h>
#include <cstdint>
#include <math.h>

// Problem constants
constexpr int M_ROWS = 65536;   // B*S*G
constexpr int N_V    = 320;
constexpr int K_D    = 384;
constexpr int OUT_D  = 768;
constexpr int GV     = 640;
constexpr float EPS_G  = 1e-10f;
constexpr float MARGIN = 0.405f;

// Device-global scratch (no allocation allowed)
__device__ __nv_bfloat16 g_z_bf16[M_ROWS * K_D];
__device__ __nv_bfloat16 g_Wt_bf16[N_V * K_D];     // W_logits^T bf16 [320][384]
__device__ float         g_Wt_f32 [N_V * K_D];     // W_logits^T fp32
__device__ float         g_E[GV * OUT_D];          // codebook@W_out fused table

__device__ __forceinline__ float gumbel_acc(float u) {
    return -logf(-logf(u + EPS_G) + EPS_G);
}
__device__ __forceinline__ float gumbel_fast(float u) {
    if (u > 0.999f) return gumbel_acc(u);
    float w = -__logf(u + EPS_G) + EPS_G;
    return -__logf(w);
}

__device__ __forceinline__ void ldsm_x4(uint32_t* r, const void* p) {
    uint32_t addr = (uint32_t)__cvta_generic_to_shared(p);
    asm volatile("ldmatrix.sync.aligned.m8n8.x4.shared.b16 {%0,%1,%2,%3}, [%4];\n"
        : "=r"(r[0]), "=r"(r[1]), "=r"(r[2]), "=r"(r[3]) : "r"(addr));
}
__device__ __forceinline__ void mma_bf16(float* c, const uint32_t* a, const uint32_t* b) {
    asm volatile("mma.sync.aligned.m16n8k16.row.col.f32.bf16.bf16.f32 "
        "{%0,%1,%2,%3}, {%4,%5,%6,%7}, {%8,%9}, {%0,%1,%2,%3};\n"
        : "+f"(c[0]), "+f"(c[1]), "+f"(c[2]), "+f"(c[3])
        : "r"(a[0]), "r"(a[1]), "r"(a[2]), "r"(a[3]), "r"(b[0]), "r"(b[1]));
}
__device__ __forceinline__ void cp16(void* dst_smem, const void* src) {
    uint32_t d = (uint32_t)__cvta_generic_to_shared(dst_smem);
    asm volatile("cp.async.cg.shared.global [%0], [%1], 16;\n" :: "r"(d), "l"(src));
}
#define CP_COMMIT() asm volatile("cp.async.commit_group;\n")
#define CP_WAIT1()  asm volatile("cp.async.wait_group 1;\n")
#define CP_WAIT0()  asm volatile("cp.async.wait_group 0;\n")

// ---------------------------------------------------------------------------
// Kernel 0a: W_logits [384][320] -> transposed bf16 + fp32
// ---------------------------------------------------------------------------
__global__ void prep_wt_kernel(const float* __restrict__ W) {
    int i = blockIdx.x * blockDim.x + threadIdx.x;
    if (i < K_D * N_V) {
        int k = i / N_V, n = i % N_V;
        float v = W[i];
        g_Wt_f32 [n * K_D + k] = v;
        g_Wt_bf16[n * K_D + k] = __float2bfloat16(v);
    }
}

// ---------------------------------------------------------------------------
// Kernel 0b: z fp32 -> bf16
// ---------------------------------------------------------------------------
__global__ __launch_bounds__(256) void convert_z_kernel(const float* __restrict__ z) {
    size_t base = ((size_t)blockIdx.x * 256 + threadIdx.x) * 8;
    float4 a = *reinterpret_cast<const float4*>(z + base);
    float4 b = *reinterpret_cast<const float4*>(z + base + 4);
    __nv_bfloat162 p0 = __floats2bfloat162_rn(a.x, a.y);
    __nv_bfloat162 p1 = __floats2bfloat162_rn(a.z, a.w);
    __nv_bfloat162 p2 = __floats2bfloat162_rn(b.x, b.y);
    __nv_bfloat162 p3 = __floats2bfloat162_rn(b.z, b.w);
    uint4 o;
    o.x = *reinterpret_cast<uint32_t*>(&p0);
    o.y = *reinterpret_cast<uint32_t*>(&p1);
    o.z = *reinterpret_cast<uint32_t*>(&p2);
    o.w = *reinterpret_cast<uint32_t*>(&p3);
    *reinterpret_cast<uint4*>(&g_z_bf16[base]) = o;
}

// ---------------------------------------------------------------------------
// Kernel 1: E[gv][o] = codebooks[gv] @ W_out-half
// ---------------------------------------------------------------------------
__global__ __launch_bounds__(256) void compute_E_kernel(
    const float* __restrict__ CB, const float* __restrict__ Wout)
{
    __shared__ float As2[32][17];
    __shared__ float Bs2[16][68];
    const int t  = threadIdx.x;
    const int ty = t >> 4, tx = t & 15;
    const int gv0 = blockIdx.y * 32;
    const int o0  = blockIdx.x * 64;
    const int goff = (gv0 >= 320) ? 384 : 0;
    float acc0[4] = {0.f,0.f,0.f,0.f}, acc1[4] = {0.f,0.f,0.f,0.f};

    for (int k0 = 0; k0 < K_D; k0 += 16) {
        #pragma unroll
        for (int i = 0; i < 2; ++i) {
            int idx = t + i * 256;
            int r = idx >> 4, c = idx & 15;
            As2[r][c] = CB[(size_t)(gv0 + r) * K_D + k0 + c];
        }
        #pragma unroll
        for (int i = 0; i < 4; ++i) {
            int idx = t + i * 256;
            int r = idx >> 6, c = idx & 63;
            Bs2[r][c] = Wout[(size_t)(goff + k0 + r) * OUT_D + o0 + c];
        }
        __syncthreads();
        #pragma unroll
        for (int k = 0; k < 16; ++k) {
            float a0 = As2[ty][k], a1 = As2[ty + 16][k];
            #pragma unroll
            for (int j = 0; j < 4; ++j) {
                float b = Bs2[k][tx * 4 + j];
                acc0[j] = fmaf(a0, b, acc0[j]);
                acc1[j] = fmaf(a1, b, acc1[j]);
            }
        }
        __syncthreads();
    }
    #pragma unroll
    for (int j = 0; j < 4; ++j) {
        g_E[(size_t)(gv0 + ty)      * OUT_D + o0 + tx * 4 + j] = acc0[j];
        g_E[(size_t)(gv0 + ty + 16) * OUT_D + o0 + tx * 4 + j] = acc1[j];
    }
}

// ---------------------------------------------------------------------------
// Kernel 2: BM=64 pipelined bf16 GEMM + noise prefetch + argmax + rescue + out
//   512 threads (16 warps: 4m x 4n), 3-stage cp.async, grid 1024
// ---------------------------------------------------------------------------
constexpr int STAGE_BYTES = 64 * 40 * 2 + 320 * 40 * 2;      // 5120 + 25600 = 30720
constexpr int NOISE_OFF   = 3 * STAGE_BYTES;                 // 92160
constexpr int NOISE_PITCH = 324;                              // floats (pad 4)
constexpr int SMEM_MAIN   = NOISE_OFF + 64 * NOISE_PITCH * 4; // 92160 + 82944 = 175104

__global__ __launch_bounds__(512, 1) void main_kernel(
    const float* __restrict__ z, const float* __restrict__ noise,
    const float* __restrict__ blog, const float* __restrict__ bout,
    float* __restrict__ out)
{
    extern __shared__ __align__(16) unsigned char sm[];
    const int tid  = threadIdx.x;
    const int lane = tid & 31, wid = tid >> 5;
    const int warp_m = wid & 3, warp_n = wid >> 2;
    const int row0 = blockIdx.x * 64;

    float* noiseS = (float*)(sm + NOISE_OFF);

    float acc[10][4];
    #pragma unroll
    for (int t = 0; t < 10; ++t)
        #pragma unroll
        for (int j = 0; j < 4; ++j) acc[t][j] = 0.f;

    auto As = [&](int s) { return (__nv_bfloat16*)(sm + s * STAGE_BYTES); };
    auto Ws = [&](int s) { return (__nv_bfloat16*)(sm + s * STAGE_BYTES + 5120); };

    auto issue = [&](int kt) {
        if (kt < 12) {
            const int k0 = kt * 32, s = kt % 3;
            if (tid < 256) {   // A tile: 64 rows x 32 bf16 = 256 x 16B
                int r = tid >> 2, c8 = (tid & 3) * 8;
                cp16(As(s) + r * 40 + c8, &g_z_bf16[(size_t)(row0 + r) * K_D + k0 + c8]);
            }
            #pragma unroll
            for (int i = 0; i < 3; ++i) {   // W tile: 320 x 32 = 1280 x 16B
                int idx = tid + i * 512;
                if (idx < 1280) {
                    int r = idx >> 2, c8 = (idx & 3) * 8;
                    cp16(Ws(s) + r * 40 + c8, &g_Wt_bf16[(size_t)r * K_D + k0 + c8]);
                }
            }
            if (kt < 10) {     // noise tile: 64 x 320 fp32 = 5120 x 16B over 10 iters
                int q = kt * 512 + tid;
                int r = q / 80, c16 = q % 80;
                cp16(&noiseS[r * NOISE_PITCH + c16 * 4],
                     &noise[(size_t)(row0 + r) * N_V + c16 * 4]);
            }
        }
        CP_COMMIT();
    };
    issue(0); issue(1);

    const int li = lane & 7, lj = lane >> 3;
    for (int kt = 0; kt < 12; ++kt) {
        CP_WAIT1();
        __syncthreads();
        issue(kt + 2);
        const __nv_bfloat16* A = As(kt % 3);
        const __nv_bfloat16* W = Ws(kt % 3);
        #pragma unroll
        for (int ks = 0; ks < 2; ++ks) {
            const int kk = ks * 16;
            uint32_t a[4];
            {
                int r = warp_m * 16 + (lj & 1) * 8 + li;
                int c = kk + (lj >> 1) * 8;
                ldsm_x4(a, &A[r * 40 + c]);
            }
            #pragma unroll
            for (int p = 0; p < 5; ++p) {
                uint32_t b[4];
                int r = warp_n * 80 + p * 16 + (lj >> 1) * 8 + li;
                int c = kk + (lj & 1) * 8;
                ldsm_x4(b, &W[r * 40 + c]);
                mma_bf16(acc[2 * p],     a, b);
                mma_bf16(acc[2 * p + 1], a, b + 2);
            }
        }
    }
    CP_WAIT0();
    __syncthreads();   // stage smem dead; noiseS live

    // ---- epilogue smem (aliases stage 0) ------------------------------------
    float* partV = (float*)sm;              // [64][4]
    int*   partC = (int*)(sm + 1024);       // [64][4]
    float* bestv = (float*)(sm + 2048);     // [64]
    int*   bestc = (int*)(sm + 2304);       // [64]
    int*   idxs  = (int*)(sm + 2560);       // [64]
    int*   ccnt  = (int*)(sm + 2816);       // [64]
    int*   clist = (int*)(sm + 3072);       // [64][8]

    // Phase A: bias + gumbel (noise from smem), per-warp partial argmax
    const int gid = lane >> 2, tig = lane & 3;
    #pragma unroll
    for (int h = 0; h < 2; ++h) {
        const int rl = warp_m * 16 + gid + 8 * h;
        float best = -1e30f; int bc = 0;
        #pragma unroll
        for (int t = 0; t < 10; ++t) {
            const int col = warp_n * 80 + t * 8 + 2 * tig;
            float2 u = *reinterpret_cast<const float2*>(&noiseS[rl * NOISE_PITCH + col]);
            float v0 = acc[t][2*h]   + __ldg(&blog[col])   + gumbel_fast(u.x);
            float v1 = acc[t][2*h+1] + __ldg(&blog[col+1]) + gumbel_fast(u.y);
            acc[t][2*h] = v0; acc[t][2*h+1] = v1;
            if (v0 > best) { best = v0; bc = col; }
            if (v1 > best) { best = v1; bc = col + 1; }
        }
        #pragma unroll
        for (int off = 1; off <= 2; off <<= 1) {
            float ov = __shfl_xor_sync(0xffffffffu, best, off);
            int   oc = __shfl_xor_sync(0xffffffffu, bc, off);
            if (ov > best || (ov == best && oc < bc)) { best = ov; bc = oc; }
        }
        if (tig == 0) { partV[rl * 4 + warp_n] = best; partC[rl * 4 + warp_n] = bc; }
    }
    __syncthreads();

    // Phase B: reduce across 4 warp_n partials (16 warps x 4 rows, 8 lanes/row)
    {
        const int rl = wid * 4 + (lane >> 3);
        const int p  = lane & 7;
        float v = partV[rl * 4 + (p & 3)]; int c = partC[rl * 4 + (p & 3)];
        #pragma unroll
        for (int off = 1; off <= 2; off <<= 1) {
            float ov = __shfl_xor_sync(0xffffffffu, v, off);
            int   oc = __shfl_xor_sync(0xffffffffu, c, off);
            if (ov > v || (ov == v && oc < c)) { v = ov; c = oc; }
        }
        if (p == 0) { bestv[rl] = v; bestc[rl] = c; idxs[rl] = c; ccnt[rl] = 0; }
    }
    __syncthreads();

    // Phase C: candidate scan (values in registers)
    #pragma unroll
    for (int h = 0; h < 2; ++h) {
        const int rl = warp_m * 16 + gid + 8 * h;
        const float thr = bestv[rl] - MARGIN;
        const int mybc = bestc[rl];
        #pragma unroll
        for (int t = 0; t < 10; ++t) {
            const int col = warp_n * 80 + t * 8 + 2 * tig;
            #pragma unroll
            for (int c2 = 0; c2 < 2; ++c2) {
                float v = acc[t][2*h + c2];
                int col2 = col + c2;
                if (v >= thr && col2 != mybc) {
                    int pos = atomicAdd(&ccnt[rl], 1);
                    if (pos < 8) clist[rl * 8 + pos] = col2;
                }
            }
        }
    }
    __syncthreads();

    // Phase D: fp64 rescue (one warp per row, round-robin)
    for (int rl = wid; rl < 64; rl += 16) {
        const int nc = ccnt[rl];
        if (nc == 0) continue;
        const size_t gRow = row0 + rl;
        const float* zr = &z[gRow * K_D];
        double bb = -1e300; int bbc = 0x7fffffff;

        auto score = [&](int col) {
            const float* wr = &g_Wt_f32[(size_t)col * K_D];
            double s0 = 0.0, s1 = 0.0, s2 = 0.0, s3 = 0.0;
            #pragma unroll
            for (int i = 0; i < 12; i += 4) {
                int k = i * 32 + lane;
                s0 += (double)zr[k]       * (double)wr[k];
                s1 += (double)zr[k + 32]  * (double)wr[k + 32];
                s2 += (double)zr[k + 64]  * (double)wr[k + 64];
                s3 += (double)zr[k + 96]  * (double)wr[k + 96];
            }
            double s = (s0 + s1) + (s2 + s3);
            #pragma unroll
            for (int off = 16; off; off >>= 1)
                s += __shfl_xor_sync(0xffffffffu, s, off);
            float u = __ldg(&noise[gRow * N_V + col]);
            double lg = s + (double)__ldg(&blog[col]) + (double)gumbel_acc(u);
            if (lg > bb || (lg == bb && col < bbc)) { bb = lg; bbc = col; }
        };

        if (nc > 8) {
            for (int col = 0; col < N_V; ++col) score(col);
        } else {
            score(bestc[rl]);
            for (int q = 0; q < nc; ++q) score(clist[rl * 8 + q]);
        }
        if (lane == 0) idxs[rl] = bbc;
    }
    __syncthreads();

    // Phase E: fused output — 32 tokens: out = E[i0] + E[320+i1] + b_out
    {
        const int tl = tid >> 4;            // token 0..31
        const int j0 = tid & 15;
        const int i0 = idxs[2 * tl];
        const int i1 = idxs[2 * tl + 1];
        const float4* e0 = reinterpret_cast<const float4*>(&g_E[(size_t)i0 * OUT_D]);
        const float4* e1 = reinterpret_cast<const float4*>(&g_E[(size_t)(320 + i1) * OUT_D]);
        const float4* b4 = reinterpret_cast<const float4*>(bout);
        float4* o4 = reinterpret_cast<float4*>(&out[(size_t)(row0 / 2 + tl) * OUT_D]);
        #pragma unroll
        for (int c = j0; c < 192; c += 16) {
            float4 a = e0[c], b = e1[c], bb2 = b4[c];
            o4[c] = make_float4(a.x + b.x + bb2.x, a.y + b.y + bb2.y,
                                a.z + b.z + bb2.z, a.w + b.w + bb2.w);
        }
    }
}

// ---------------------------------------------------------------------------
extern "C" void kernel_launch(void* const* d_in, const int* in_sizes, int n_in,
                              void* d_out, int out_size)
{
    const float *z = nullptr, *noise = nullptr, *Wlog = nullptr, *blog = nullptr,
                *CB = nullptr, *Wout = nullptr, *bout = nullptr;
    for (int i = 0; i < n_in; ++i) {
        switch (in_sizes[i]) {
            case 25165824: z     = (const float*)d_in[i]; break;
            case 20971520: noise = (const float*)d_in[i]; break;
            case 122880:   Wlog  = (const float*)d_in[i]; break;
            case 320:      blog  = (const float*)d_in[i]; break;
            case 245760:   CB    = (const float*)d_in[i]; break;
            case 589824:   Wout  = (const float*)d_in[i]; break;
            case 768:      bout  = (const float*)d_in[i]; break;
        }
    }
    float* out = (float*)d_out;

    static bool attr_set = false;
    if (!attr_set) {
        cudaFuncSetAttribute(main_kernel,
            cudaFuncAttributeMaxDynamicSharedMemorySize, SMEM_MAIN);
        attr_set = true;
    }

    prep_wt_kernel<<<(N_V * K_D + 255) / 256, 256>>>(Wlog);
    convert_z_kernel<<<M_ROWS * K_D / (256 * 8), 256>>>(z);
    compute_E_kernel<<<dim3(OUT_D / 64, GV / 32), 256>>>(CB, Wout);
    main_kernel<<<M_ROWS / 64, 512, SMEM_MAIN>>>(z, noise, blog, bout, out);
}

// round 5
// speedup vs baseline: 2.2829x; 2.2829x over previous
#include <cuda_runtime.h>
#include <cuda_bf16.h>
#include <cstdint>
#include <math.h>

// Problem constants
constexpr int M_ROWS = 65536;   // B*S*G
constexpr int N_V    = 320;
constexpr int K_D    = 384;
constexpr int OUT_D  = 768;
constexpr int GV     = 640;
constexpr float EPS_G  = 1e-10f;
constexpr float MARGIN = 0.405f;

// Device-global scratch (no allocation allowed)
__device__ __nv_bfloat16 g_z_bf16[M_ROWS * K_D];
__device__ __nv_bfloat16 g_Wt_bf16[N_V * K_D];     // W_logits^T bf16 [320][384]
__device__ float         g_Wt_f32 [N_V * K_D];     // W_logits^T fp32
__device__ float         g_E[GV * OUT_D];          // codebook@W_out fused table

__device__ __forceinline__ float gumbel_acc(float u) {
    return -logf(-logf(u + EPS_G) + EPS_G);
}
__device__ __forceinline__ float gumbel_fast(float u) {
    if (u > 0.999f) return gumbel_acc(u);
    float w = -__logf(u + EPS_G) + EPS_G;
    return -__logf(w);
}

// Knuth two-sum: s,c += v (exactly, compensated)
__device__ __forceinline__ void two_sum(float& s, float& c, float v) {
    float t  = s + v;
    float bv = t - s;
    float err = (s - (t - bv)) + (v - bv);
    s = t; c += err;
}

__device__ __forceinline__ void ldsm_x4(uint32_t* r, const void* p) {
    uint32_t addr = (uint32_t)__cvta_generic_to_shared(p);
    asm volatile("ldmatrix.sync.aligned.m8n8.x4.shared.b16 {%0,%1,%2,%3}, [%4];\n"
        : "=r"(r[0]), "=r"(r[1]), "=r"(r[2]), "=r"(r[3]) : "r"(addr));
}
__device__ __forceinline__ void mma_bf16(float* c, const uint32_t* a, const uint32_t* b) {
    asm volatile("mma.sync.aligned.m16n8k16.row.col.f32.bf16.bf16.f32 "
        "{%0,%1,%2,%3}, {%4,%5,%6,%7}, {%8,%9}, {%0,%1,%2,%3};\n"
        : "+f"(c[0]), "+f"(c[1]), "+f"(c[2]), "+f"(c[3])
        : "r"(a[0]), "r"(a[1]), "r"(a[2]), "r"(a[3]), "r"(b[0]), "r"(b[1]));
}
__device__ __forceinline__ void cp16(void* dst_smem, const void* src) {
    uint32_t d = (uint32_t)__cvta_generic_to_shared(dst_smem);
    asm volatile("cp.async.cg.shared.global [%0], [%1], 16;\n" :: "r"(d), "l"(src));
}
#define CP_COMMIT() asm volatile("cp.async.commit_group;\n")
#define CP_WAIT1()  asm volatile("cp.async.wait_group 1;\n")
#define CP_WAIT0()  asm volatile("cp.async.wait_group 0;\n")

// ---------------------------------------------------------------------------
// Kernel 0a: W_logits [384][320] -> transposed bf16 + fp32
// ---------------------------------------------------------------------------
__global__ void prep_wt_kernel(const float* __restrict__ W) {
    int i = blockIdx.x * blockDim.x + threadIdx.x;
    if (i < K_D * N_V) {
        int k = i / N_V, n = i % N_V;
        float v = W[i];
        g_Wt_f32 [n * K_D + k] = v;
        g_Wt_bf16[n * K_D + k] = __float2bfloat16(v);
    }
}

// ---------------------------------------------------------------------------
// Kernel 0b: z fp32 -> bf16
// ---------------------------------------------------------------------------
__global__ __launch_bounds__(256) void convert_z_kernel(const float* __restrict__ z) {
    size_t base = ((size_t)blockIdx.x * 256 + threadIdx.x) * 8;
    float4 a = *reinterpret_cast<const float4*>(z + base);
    float4 b = *reinterpret_cast<const float4*>(z + base + 4);
    __nv_bfloat162 p0 = __floats2bfloat162_rn(a.x, a.y);
    __nv_bfloat162 p1 = __floats2bfloat162_rn(a.z, a.w);
    __nv_bfloat162 p2 = __floats2bfloat162_rn(b.x, b.y);
    __nv_bfloat162 p3 = __floats2bfloat162_rn(b.z, b.w);
    uint4 o;
    o.x = *reinterpret_cast<uint32_t*>(&p0);
    o.y = *reinterpret_cast<uint32_t*>(&p1);
    o.z = *reinterpret_cast<uint32_t*>(&p2);
    o.w = *reinterpret_cast<uint32_t*>(&p3);
    *reinterpret_cast<uint4*>(&g_z_bf16[base]) = o;
}

// ---------------------------------------------------------------------------
// Kernel 1: E[gv][o] = codebooks[gv] @ W_out-half
// ---------------------------------------------------------------------------
__global__ __launch_bounds__(256) void compute_E_kernel(
    const float* __restrict__ CB, const float* __restrict__ Wout)
{
    __shared__ float As2[32][17];
    __shared__ float Bs2[16][68];
    const int t  = threadIdx.x;
    const int ty = t >> 4, tx = t & 15;
    const int gv0 = blockIdx.y * 32;
    const int o0  = blockIdx.x * 64;
    const int goff = (gv0 >= 320) ? 384 : 0;
    float acc0[4] = {0.f,0.f,0.f,0.f}, acc1[4] = {0.f,0.f,0.f,0.f};

    for (int k0 = 0; k0 < K_D; k0 += 16) {
        #pragma unroll
        for (int i = 0; i < 2; ++i) {
            int idx = t + i * 256;
            int r = idx >> 4, c = idx & 15;
            As2[r][c] = CB[(size_t)(gv0 + r) * K_D + k0 + c];
        }
        #pragma unroll
        for (int i = 0; i < 4; ++i) {
            int idx = t + i * 256;
            int r = idx >> 6, c = idx & 63;
            Bs2[r][c] = Wout[(size_t)(goff + k0 + r) * OUT_D + o0 + c];
        }
        __syncthreads();
        #pragma unroll
        for (int k = 0; k < 16; ++k) {
            float a0 = As2[ty][k], a1 = As2[ty + 16][k];
            #pragma unroll
            for (int j = 0; j < 4; ++j) {
                float b = Bs2[k][tx * 4 + j];
                acc0[j] = fmaf(a0, b, acc0[j]);
                acc1[j] = fmaf(a1, b, acc1[j]);
            }
        }
        __syncthreads();
    }
    #pragma unroll
    for (int j = 0; j < 4; ++j) {
        g_E[(size_t)(gv0 + ty)      * OUT_D + o0 + tx * 4 + j] = acc0[j];
        g_E[(size_t)(gv0 + ty + 16) * OUT_D + o0 + tx * 4 + j] = acc1[j];
    }
}

// ---------------------------------------------------------------------------
// Kernel 2: BM=64 pipelined bf16 GEMM + argmax + fp32-compensated rescue + out
//   512 threads (16 warps: 4m x 4n), 3-stage cp.async, grid 1024
// ---------------------------------------------------------------------------
constexpr int STAGE_BYTES = 64 * 40 * 2 + 320 * 40 * 2;   // 30720
constexpr int SMEM_MAIN   = 3 * STAGE_BYTES;              // 92160

__global__ __launch_bounds__(512, 1) void main_kernel(
    const float* __restrict__ z, const float* __restrict__ noise,
    const float* __restrict__ blog, const float* __restrict__ bout,
    float* __restrict__ out)
{
    extern __shared__ __align__(16) unsigned char sm[];
    const int tid  = threadIdx.x;
    const int lane = tid & 31, wid = tid >> 5;
    const int warp_m = wid & 3, warp_n = wid >> 2;
    const int row0 = blockIdx.x * 64;

    float acc[10][4];
    #pragma unroll
    for (int t = 0; t < 10; ++t)
        #pragma unroll
        for (int j = 0; j < 4; ++j) acc[t][j] = 0.f;

    auto As = [&](int s) { return (__nv_bfloat16*)(sm + s * STAGE_BYTES); };
    auto Ws = [&](int s) { return (__nv_bfloat16*)(sm + s * STAGE_BYTES + 5120); };

    auto issue = [&](int kt) {
        if (kt < 12) {
            const int k0 = kt * 32, s = kt % 3;
            if (tid < 256) {   // A tile: 64 rows x 32 bf16 = 256 x 16B
                int r = tid >> 2, c8 = (tid & 3) * 8;
                cp16(As(s) + r * 40 + c8, &g_z_bf16[(size_t)(row0 + r) * K_D + k0 + c8]);
            }
            #pragma unroll
            for (int i = 0; i < 3; ++i) {   // W tile: 320 x 32 = 1280 x 16B
                int idx = tid + i * 512;
                if (idx < 1280) {
                    int r = idx >> 2, c8 = (idx & 3) * 8;
                    cp16(Ws(s) + r * 40 + c8, &g_Wt_bf16[(size_t)r * K_D + k0 + c8]);
                }
            }
        }
        CP_COMMIT();
    };
    issue(0); issue(1);

    const int li = lane & 7, lj = lane >> 3;
    for (int kt = 0; kt < 12; ++kt) {
        CP_WAIT1();
        __syncthreads();
        issue(kt + 2);
        const __nv_bfloat16* A = As(kt % 3);
        const __nv_bfloat16* W = Ws(kt % 3);
        #pragma unroll
        for (int ks = 0; ks < 2; ++ks) {
            const int kk = ks * 16;
            uint32_t a[4];
            {
                int r = warp_m * 16 + (lj & 1) * 8 + li;
                int c = kk + (lj >> 1) * 8;
                ldsm_x4(a, &A[r * 40 + c]);
            }
            #pragma unroll
            for (int p = 0; p < 5; ++p) {
                uint32_t b[4];
                int r = warp_n * 80 + p * 16 + (lj >> 1) * 8 + li;
                int c = kk + (lj & 1) * 8;
                ldsm_x4(b, &W[r * 40 + c]);
                mma_bf16(acc[2 * p],     a, b);
                mma_bf16(acc[2 * p + 1], a, b + 2);
            }
        }
    }
    CP_WAIT0();
    __syncthreads();   // stage smem dead; repurpose below

    // ---- epilogue smem (aliases stage 0) ------------------------------------
    float* partV = (float*)sm;              // [64][4]
    int*   partC = (int*)(sm + 1024);       // [64][4]
    float* bestv = (float*)(sm + 2048);     // [64]
    int*   bestc = (int*)(sm + 2304);       // [64]
    int*   idxs  = (int*)(sm + 2560);       // [64]
    int*   ccnt  = (int*)(sm + 2816);       // [64]
    int*   clist = (int*)(sm + 3072);       // [64][8]

    // Phase A: bias + gumbel (noise from gmem, coalesced), partial argmax
    const int gid = lane >> 2, tig = lane & 3;
    #pragma unroll
    for (int h = 0; h < 2; ++h) {
        const int rl = warp_m * 16 + gid + 8 * h;
        const size_t gRow = row0 + rl;
        float best = -1e30f; int bc = 0;
        #pragma unroll
        for (int t = 0; t < 10; ++t) {
            const int col = warp_n * 80 + t * 8 + 2 * tig;
            float2 u = *reinterpret_cast<const float2*>(&noise[gRow * N_V + col]);
            float v0 = acc[t][2*h]   + __ldg(&blog[col])   + gumbel_fast(u.x);
            float v1 = acc[t][2*h+1] + __ldg(&blog[col+1]) + gumbel_fast(u.y);
            acc[t][2*h] = v0; acc[t][2*h+1] = v1;
            if (v0 > best) { best = v0; bc = col; }
            if (v1 > best) { best = v1; bc = col + 1; }
        }
        #pragma unroll
        for (int off = 1; off <= 2; off <<= 1) {
            float ov = __shfl_xor_sync(0xffffffffu, best, off);
            int   oc = __shfl_xor_sync(0xffffffffu, bc, off);
            if (ov > best || (ov == best && oc < bc)) { best = ov; bc = oc; }
        }
        if (tig == 0) { partV[rl * 4 + warp_n] = best; partC[rl * 4 + warp_n] = bc; }
    }
    __syncthreads();

    // Phase B: reduce across 4 warp_n partials
    {
        const int rl = wid * 4 + (lane >> 3);
        const int p  = lane & 7;
        float v = partV[rl * 4 + (p & 3)]; int c = partC[rl * 4 + (p & 3)];
        #pragma unroll
        for (int off = 1; off <= 2; off <<= 1) {
            float ov = __shfl_xor_sync(0xffffffffu, v, off);
            int   oc = __shfl_xor_sync(0xffffffffu, c, off);
            if (ov > v || (ov == v && oc < c)) { v = ov; c = oc; }
        }
        if (p == 0) { bestv[rl] = v; bestc[rl] = c; idxs[rl] = c; ccnt[rl] = 0; }
    }
    __syncthreads();

    // Phase C: candidate scan (values in registers)
    #pragma unroll
    for (int h = 0; h < 2; ++h) {
        const int rl = warp_m * 16 + gid + 8 * h;
        const float thr = bestv[rl] - MARGIN;
        const int mybc = bestc[rl];
        #pragma unroll
        for (int t = 0; t < 10; ++t) {
            const int col = warp_n * 80 + t * 8 + 2 * tig;
            #pragma unroll
            for (int c2 = 0; c2 < 2; ++c2) {
                float v = acc[t][2*h + c2];
                int col2 = col + c2;
                if (v >= thr && col2 != mybc) {
                    int pos = atomicAdd(&ccnt[rl], 1);
                    if (pos < 8) clist[rl * 8 + pos] = col2;
                }
            }
        }
    }
    __syncthreads();

    // Phase D: compensated-fp32 rescue (NO fp64 — decimated on B300)
    for (int rl = wid; rl < 64; rl += 16) {
        const int nc = ccnt[rl];
        if (nc == 0) continue;
        const size_t gRow = row0 + rl;
        const float* zr = &z[gRow * K_D];
        float bhi = -1e30f, blo = 0.f; int bbc = 0x7fffffff;

        auto score = [&](int col) {
            const float* wr = &g_Wt_f32[(size_t)col * K_D];
            float s = 0.f, c = 0.f;
            #pragma unroll
            for (int i = 0; i < 12; ++i) {
                int k = i * 32 + lane;
                float a = zr[k], b = wr[k];
                float p = a * b;
                float e = fmaf(a, b, -p);      // exact product residual
                two_sum(s, c, p);
                c += e;
            }
            // compensated warp reduction
            #pragma unroll
            for (int off = 16; off; off >>= 1) {
                float so = __shfl_xor_sync(0xffffffffu, s, off);
                float co = __shfl_xor_sync(0xffffffffu, c, off);
                two_sum(s, c, so);
                c += co;
            }
            float u = __ldg(&noise[gRow * N_V + col]);
            float base = __ldg(&blog[col]) + gumbel_acc(u);
            two_sum(s, c, base);
            // compare as (hi, lo) pair
            bool gt = (s > bhi) || (s == bhi && (c > blo || (c == blo && col < bbc)));
            if (gt) { bhi = s; blo = c; bbc = col; }
        };

        if (nc > 8) {
            for (int col = 0; col < N_V; ++col) score(col);
        } else {
            score(bestc[rl]);
            for (int q = 0; q < nc; ++q) score(clist[rl * 8 + q]);
        }
        if (lane == 0) idxs[rl] = bbc;
    }
    __syncthreads();

    // Phase E: fused output — 32 tokens: out = E[i0] + E[320+i1] + b_out
    {
        const int tl = tid >> 4;            // token 0..31
        const int j0 = tid & 15;
        const int i0 = idxs[2 * tl];
        const int i1 = idxs[2 * tl + 1];
        const float4* e0 = reinterpret_cast<const float4*>(&g_E[(size_t)i0 * OUT_D]);
        const float4* e1 = reinterpret_cast<const float4*>(&g_E[(size_t)(320 + i1) * OUT_D]);
        const float4* b4 = reinterpret_cast<const float4*>(bout);
        float4* o4 = reinterpret_cast<float4*>(&out[(size_t)(row0 / 2 + tl) * OUT_D]);
        #pragma unroll
        for (int c = j0; c < 192; c += 16) {
            float4 a = e0[c], b = e1[c], bb2 = b4[c];
            o4[c] = make_float4(a.x + b.x + bb2.x, a.y + b.y + bb2.y,
                                a.z + b.z + bb2.z, a.w + b.w + bb2.w);
        }
    }
}

// ---------------------------------------------------------------------------
extern "C" void kernel_launch(void* const* d_in, const int* in_sizes, int n_in,
                              void* d_out, int out_size)
{
    const float *z = nullptr, *noise = nullptr, *Wlog = nullptr, *blog = nullptr,
                *CB = nullptr, *Wout = nullptr, *bout = nullptr;
    for (int i = 0; i < n_in; ++i) {
        switch (in_sizes[i]) {
            case 25165824: z     = (const float*)d_in[i]; break;
            case 20971520: noise = (const float*)d_in[i]; break;
            case 122880:   Wlog  = (const float*)d_in[i]; break;
            case 320:      blog  = (const float*)d_in[i]; break;
            case 245760:   CB    = (const float*)d_in[i]; break;
            case 589824:   Wout  = (const float*)d_in[i]; break;
            case 768:      bout  = (const float*)d_in[i]; break;
        }
    }
    float* out = (float*)d_out;

    static bool attr_set = false;
    if (!attr_set) {
        cudaFuncSetAttribute(main_kernel,
            cudaFuncAttributeMaxDynamicSharedMemorySize, SMEM_MAIN);
        attr_set = true;
    }

    prep_wt_kernel<<<(N_V * K_D + 255) / 256, 256>>>(Wlog);
    convert_z_kernel<<<M_ROWS * K_D / (256 * 8), 256>>>(z);
    compute_E_kernel<<<dim3(OUT_D / 64, GV / 32), 256>>>(CB, Wout);
    main_kernel<<<M_ROWS / 64, 512, SMEM_MAIN>>>(z, noise, blog, bout, out);
}